// round 3
// baseline (speedup 1.0000x reference)
#include <cuda_runtime.h>

// GAT autoencoder: 4 GATConv layers (64->64 relu, 64->32 [h out], relu,
// 32->64 relu, 64->64 [out]). Edges = edge_index (800k) + self loops (N).
// Outputs concatenated: out [N*64] then h [N*32].
//
// edge_index dtype is detected at runtime (harness may downcast int64->int32).

#define MAXN 50000
#define MAXE 800000
#define MAXET (MAXE + MAXN)

// ---------------- scratch (no allocations allowed) ----------------
__device__ __align__(16) float g_featA[MAXN * 64];
__device__ __align__(16) float g_featB[MAXN * 64];
__device__ __align__(16) float g_h[MAXN * 64];
__device__ __align__(16) float g_agg[MAXN * 64];
__device__ float g_ssrc[MAXN];
__device__ float g_sdst[MAXN];
__device__ float g_m[MAXN];
__device__ float g_den[MAXN];
__device__ float g_e[MAXET];
__device__ int   g_src[MAXET];
__device__ int   g_dst[MAXET];
__device__ int   g_is64;

// buffer selector: 1 = g_featA, 2 = g_featB (0 = external pointer)
__device__ __forceinline__ const float* pick_src(int sel, const float* ext) {
    if (sel == 1) return g_featA;
    if (sel == 2) return g_featB;
    return ext;
}
__device__ __forceinline__ float* pick_dst(int sel) {
    if (sel == 1) return g_featA;
    if (sel == 2) return g_featB;
    return nullptr;
}

// ---------------- kernels ----------------

// Detect whether edge_index buffer holds int64 (odd 32-bit words all zero)
// or int32 (odd words are random node ids). Reads only the first 1KB.
__global__ void k_detect(const unsigned int* __restrict__ w, int nelem) {
    if (threadIdx.x != 0 || blockIdx.x != 0) return;
    int lim = 2 * nelem < 256 ? 2 * nelem : 256;  // safe in int32 layout too
    int all0 = 1;
    for (int i = 1; i < lim; i += 2)
        if (w[i] != 0) { all0 = 0; break; }
    g_is64 = all0;
}

// edge_index -> int32 src/dst, appending self loops. Clamp ids to [0, n).
__global__ void k_convert(const void* __restrict__ ei, int eraw, int n) {
    int i = blockIdx.x * 256 + threadIdx.x;
    int etot = eraw + n;
    if (i >= etot) return;
    if (i < eraw) {
        int s, d;
        if (g_is64) {
            const long long* p = (const long long*)ei;
            s = (int)p[i];
            d = (int)p[eraw + i];
        } else {
            const int* p = (const int*)ei;
            s = p[i];
            d = p[eraw + i];
        }
        s = s < 0 ? 0 : (s >= n ? n - 1 : s);
        d = d < 0 ? 0 : (d >= n ? n - 1 : d);
        g_src[i] = s;
        g_dst[i] = d;
    } else {
        int v = i - eraw;
        g_src[i] = v;
        g_dst[i] = v;
    }
}

// g_h = x @ W   (row-major x: [n, DI], W: [DI, DO])
template <int DI, int DO>
__global__ void k_gemm(int xsel, const float* __restrict__ xext,
                       const float* __restrict__ W, int n) {
    __shared__ float Ws[DI * DO];
    for (int i = threadIdx.x; i < DI * DO; i += 256) Ws[i] = W[i];
    __syncthreads();
    int t = blockIdx.x * 256 + threadIdx.x;
    int row = t / DO;
    int col = t - row * DO;
    if (row >= n) return;
    const float* x = pick_src(xsel, xext);
    const float4* xr = reinterpret_cast<const float4*>(x + row * DI);
    float acc = 0.f;
#pragma unroll
    for (int k4 = 0; k4 < DI / 4; k4++) {
        float4 xv = xr[k4];
        acc = fmaf(xv.x, Ws[(4 * k4 + 0) * DO + col], acc);
        acc = fmaf(xv.y, Ws[(4 * k4 + 1) * DO + col], acc);
        acc = fmaf(xv.z, Ws[(4 * k4 + 2) * DO + col], acc);
        acc = fmaf(xv.w, Ws[(4 * k4 + 3) * DO + col], acc);
    }
    g_h[row * DO + col] = acc;
}

// per-node attention scores: s_src = h . a_src, s_dst = h . a_dst
template <int DO>
__global__ void k_scores(const float* __restrict__ as_,
                         const float* __restrict__ ad_, int n) {
    int i = blockIdx.x * 256 + threadIdx.x;
    if (i >= n) return;
    const float4* hr = reinterpret_cast<const float4*>(g_h + i * DO);
    float ss = 0.f, sd = 0.f;
#pragma unroll
    for (int k = 0; k < DO / 4; k++) {
        float4 hv = hr[k];
        float4 a1 = __ldg(reinterpret_cast<const float4*>(as_) + k);
        float4 a2 = __ldg(reinterpret_cast<const float4*>(ad_) + k);
        ss += hv.x * a1.x + hv.y * a1.y + hv.z * a1.z + hv.w * a1.w;
        sd += hv.x * a2.x + hv.y * a2.y + hv.z * a2.z + hv.w * a2.w;
    }
    g_ssrc[i] = ss;
    g_sdst[i] = sd;
}

template <int DO>
__global__ void k_init(int n) {
    int i = blockIdx.x * 256 + threadIdx.x;
    if (i < n * DO) g_agg[i] = 0.f;
    if (i < n) {
        g_m[i] = __int_as_float(0xFF800000);  // -inf
        g_den[i] = 0.f;
    }
}

// pass A: e = leaky_relu(s_src[src] + s_dst[dst]); segment max via atomic bit trick
__global__ void k_edgeA(int etot) {
    int i = blockIdx.x * 256 + threadIdx.x;
    if (i >= etot) return;
    int s = g_src[i], d = g_dst[i];
    float e = g_ssrc[s] + g_sdst[d];
    e = e > 0.f ? e : 0.2f * e;
    g_e[i] = e;
    if (e >= 0.f)
        atomicMax((int*)&g_m[d], __float_as_int(e));
    else
        atomicMin((unsigned int*)&g_m[d], __float_as_uint(e));
}

// pass B: ex = exp(e - m[dst]); denom[dst] += ex
__global__ void k_edgeB(int etot) {
    int i = blockIdx.x * 256 + threadIdx.x;
    if (i >= etot) return;
    int d = g_dst[i];
    float ex = __expf(g_e[i] - g_m[d]);
    g_e[i] = ex;
    atomicAdd(&g_den[d], ex);
}

// pass C: agg[dst] += (ex/denom[dst]) * h[src] ; DO/4 threads per edge, float4 red
template <int DO>
__global__ void k_edgeC(int etot) {
    const int C = DO / 4;  // float4 chunks per row (16 or 8)
    int i = blockIdx.x * 256 + threadIdx.x;
    if (i >= etot * C) return;
    int e = i / C;
    int c = i - e * C;
    int s = g_src[e], d = g_dst[e];
    float alpha = g_e[e] / (g_den[d] + 1e-16f);
    float4 hv = reinterpret_cast<const float4*>(g_h)[s * C + c];
    float* p = g_agg + d * DO + c * 4;
    asm volatile("red.global.add.v4.f32 [%0], {%1,%2,%3,%4};" ::"l"(p),
                 "f"(alpha * hv.x), "f"(alpha * hv.y), "f"(alpha * hv.z),
                 "f"(alpha * hv.w)
                 : "memory");
}

// epilogue: v = agg + b; optional relu feature write (selector), optional raw write
template <int DO>
__global__ void k_post(const float* __restrict__ b, int featsel,
                       float* __restrict__ raw, int n) {
    int i = blockIdx.x * 256 + threadIdx.x;
    if (i >= n * DO) return;
    float v = g_agg[i] + __ldg(b + (i & (DO - 1)));
    if (raw) raw[i] = v;
    float* feat = pick_dst(featsel);
    if (feat) feat[i] = v > 0.f ? v : 0.f;
}

// ---------------- launch ----------------
extern "C" void kernel_launch(void* const* d_in, const int* in_sizes, int n_in,
                              void* d_out, int out_size) {
    const float* x = (const float*)d_in[0];
    const void* ei = d_in[1];
    const float* w1 = (const float*)d_in[2];
    const float* as1 = (const float*)d_in[3];
    const float* ad1 = (const float*)d_in[4];
    const float* b1 = (const float*)d_in[5];
    const float* w2 = (const float*)d_in[6];
    const float* as2 = (const float*)d_in[7];
    const float* ad2 = (const float*)d_in[8];
    const float* b2 = (const float*)d_in[9];
    const float* w3 = (const float*)d_in[10];
    const float* as3 = (const float*)d_in[11];
    const float* ad3 = (const float*)d_in[12];
    const float* b3 = (const float*)d_in[13];
    const float* w4 = (const float*)d_in[14];
    const float* as4 = (const float*)d_in[15];
    const float* ad4 = (const float*)d_in[16];
    const float* b4 = (const float*)d_in[17];

    int n = in_sizes[0] / 64;
    int eraw = in_sizes[1] / 2;
    int etot = eraw + n;

    float* out_sec = (float*)d_out;         // [n*64]
    float* h_sec = (float*)d_out + n * 64;  // [n*32]

    int nbE = (etot + 255) / 256;
    int nbN64 = (n * 64 + 255) / 256;
    int nbN32 = (n * 32 + 255) / 256;
    int nbN = (n + 255) / 256;
    int nbC64 = (etot * 16 + 255) / 256;
    int nbC32 = (etot * 8 + 255) / 256;

    k_detect<<<1, 32>>>((const unsigned int*)ei, in_sizes[1]);
    k_convert<<<nbE, 256>>>(ei, eraw, n);

    // ----- layer 1: x(ext) 64 -> 64, relu -> featA -----
    k_gemm<64, 64><<<nbN64, 256>>>(0, x, w1, n);
    k_scores<64><<<nbN, 256>>>(as1, ad1, n);
    k_init<64><<<nbN64, 256>>>(n);
    k_edgeA<<<nbE, 256>>>(etot);
    k_edgeB<<<nbE, 256>>>(etot);
    k_edgeC<64><<<nbC64, 256>>>(etot);
    k_post<64><<<nbN64, 256>>>(b1, 1, nullptr, n);

    // ----- layer 2: featA 64 -> 32, raw h -> d_out, relu -> featB -----
    k_gemm<64, 32><<<nbN32, 256>>>(1, nullptr, w2, n);
    k_scores<32><<<nbN, 256>>>(as2, ad2, n);
    k_init<32><<<nbN32, 256>>>(n);
    k_edgeA<<<nbE, 256>>>(etot);
    k_edgeB<<<nbE, 256>>>(etot);
    k_edgeC<32><<<nbC32, 256>>>(etot);
    k_post<32><<<nbN32, 256>>>(b2, 2, h_sec, n);

    // ----- layer 3: featB 32 -> 64, relu -> featA -----
    k_gemm<32, 64><<<nbN64, 256>>>(2, nullptr, w3, n);
    k_scores<64><<<nbN, 256>>>(as3, ad3, n);
    k_init<64><<<nbN64, 256>>>(n);
    k_edgeA<<<nbE, 256>>>(etot);
    k_edgeB<<<nbE, 256>>>(etot);
    k_edgeC<64><<<nbC64, 256>>>(etot);
    k_post<64><<<nbN64, 256>>>(b3, 1, nullptr, n);

    // ----- layer 4: featA 64 -> 64, raw -> d_out -----
    k_gemm<64, 64><<<nbN64, 256>>>(1, nullptr, w4, n);
    k_scores<64><<<nbN, 256>>>(as4, ad4, n);
    k_init<64><<<nbN64, 256>>>(n);
    k_edgeA<<<nbE, 256>>>(etot);
    k_edgeB<<<nbE, 256>>>(etot);
    k_edgeC<64><<<nbC64, 256>>>(etot);
    k_post<64><<<nbN64, 256>>>(b4, 0, out_sec, n);
}

// round 6
// speedup vs baseline: 1.3823x; 1.3823x over previous
#include <cuda_runtime.h>
#include <math_constants.h>

// GAT autoencoder, CSR-gather formulation (no atomics in hot path).
// Layers: 64->64 relu, 64->32 [h out], relu, 32->64 relu, 64->64 [out].
// Edges = edge_index (800k, runtime dtype detect) + N self loops.
// Outputs concatenated: out [N*64] then h [N*32].

#define MAXN 50000
#define MAXE 800000
#define MAXET (MAXE + MAXN)

// ---------------- scratch ----------------
__device__ __align__(16) float g_featA[MAXN * 64];
__device__ __align__(16) float g_featB[MAXN * 64];
__device__ __align__(16) float g_h[MAXN * 64];
__device__ float g_ssrc[MAXN];
__device__ float g_sdst[MAXN];
__device__ int g_src[MAXET];
__device__ int g_dst[MAXET];
__device__ int g_adj[MAXET];      // CSR: src ids grouped by dst
__device__ int g_roff[MAXN + 1];  // CSR row offsets
__device__ int g_cnt[MAXN];       // degree counts
__device__ int g_cur[MAXN];       // scatter cursors
__device__ int g_is64;

__device__ __forceinline__ const float* pick_src(int sel, const float* ext) {
    if (sel == 1) return g_featA;
    if (sel == 2) return g_featB;
    return ext;
}
__device__ __forceinline__ float* pick_dst(int sel) {
    if (sel == 1) return g_featA;
    if (sel == 2) return g_featB;
    return nullptr;
}

// ---------------- graph prep ----------------

// int64 vs int32 detection: int64 little-endian node ids < 2^31 have all
// odd 32-bit words zero.
__global__ void k_detect(const unsigned int* __restrict__ w, int nelem) {
    if (threadIdx.x != 0 || blockIdx.x != 0) return;
    int lim = 2 * nelem < 256 ? 2 * nelem : 256;
    int all0 = 1;
    for (int i = 1; i < lim; i += 2)
        if (w[i] != 0) { all0 = 0; break; }
    g_is64 = all0;
}

__global__ void k_convert(const void* __restrict__ ei, int eraw, int n) {
    int i = blockIdx.x * 256 + threadIdx.x;
    int etot = eraw + n;
    if (i >= etot) return;
    if (i < eraw) {
        int s, d;
        if (g_is64) {
            const long long* p = (const long long*)ei;
            s = (int)p[i];
            d = (int)p[eraw + i];
        } else {
            const int* p = (const int*)ei;
            s = p[i];
            d = p[eraw + i];
        }
        s = s < 0 ? 0 : (s >= n ? n - 1 : s);
        d = d < 0 ? 0 : (d >= n ? n - 1 : d);
        g_src[i] = s;
        g_dst[i] = d;
    } else {
        int v = i - eraw;
        g_src[i] = v;
        g_dst[i] = v;
    }
}

__global__ void k_zero(int n) {
    int i = blockIdx.x * 256 + threadIdx.x;
    if (i < n) g_cnt[i] = 0;
}

__global__ void k_hist(int etot) {
    int i = blockIdx.x * 256 + threadIdx.x;
    if (i < etot) atomicAdd(&g_cnt[g_dst[i]], 1);
}

// single-block exclusive scan of g_cnt -> g_roff/g_cur (n up to 50k)
__global__ void k_scan(int n) {
    __shared__ int sh[1024];
    __shared__ int s_carry;
    int tid = threadIdx.x;
    if (tid == 0) s_carry = 0;
    __syncthreads();
    for (int base = 0; base < n; base += 1024) {
        int i = base + tid;
        int v = (i < n) ? g_cnt[i] : 0;
        sh[tid] = v;
        __syncthreads();
        for (int off = 1; off < 1024; off <<= 1) {
            int t = (tid >= off) ? sh[tid - off] : 0;
            __syncthreads();
            sh[tid] += t;
            __syncthreads();
        }
        int incl = sh[tid];
        int carry = s_carry;
        if (i < n) {
            int ex = carry + incl - v;
            g_roff[i] = ex;
            g_cur[i] = ex;
        }
        __syncthreads();
        if (tid == 1023) s_carry = carry + incl;
        __syncthreads();
    }
    if (tid == 0) g_roff[n] = s_carry;
}

__global__ void k_scatter(int etot) {
    int i = blockIdx.x * 256 + threadIdx.x;
    if (i >= etot) return;
    int pos = atomicAdd(&g_cur[g_dst[i]], 1);
    g_adj[pos] = g_src[i];
}

// ---------------- fused gemm + attention scores ----------------
// warp per output row; lane covers col {l} (DO=32) or {l, l+32} (DO=64).
template <int DI, int DO>
__global__ void k_gemm_sc(int xsel, const float* __restrict__ xext,
                          const float* __restrict__ W,
                          const float* __restrict__ as_,
                          const float* __restrict__ ad_, int n) {
    __shared__ float Ws[DI * DO];
    for (int i = threadIdx.x; i < DI * DO; i += blockDim.x) Ws[i] = W[i];
    __syncthreads();
    int row = (blockIdx.x * blockDim.x + threadIdx.x) >> 5;
    int lane = threadIdx.x & 31;
    if (row >= n) return;
    const float* x = pick_src(xsel, xext) + row * DI;
    float acc0 = 0.f, acc1 = 0.f;
#pragma unroll
    for (int k0 = 0; k0 < DI; k0 += 32) {
        float xv = x[k0 + lane];
#pragma unroll
        for (int kk = 0; kk < 32; kk++) {
            float xk = __shfl_sync(0xFFFFFFFFu, xv, kk);
            acc0 = fmaf(xk, Ws[(k0 + kk) * DO + lane], acc0);
            if (DO == 64) acc1 = fmaf(xk, Ws[(k0 + kk) * DO + lane + 32], acc1);
        }
    }
    g_h[row * DO + lane] = acc0;
    if (DO == 64) g_h[row * DO + lane + 32] = acc1;
    float ss = acc0 * __ldg(as_ + lane);
    float sd = acc0 * __ldg(ad_ + lane);
    if (DO == 64) {
        ss = fmaf(acc1, __ldg(as_ + lane + 32), ss);
        sd = fmaf(acc1, __ldg(ad_ + lane + 32), sd);
    }
#pragma unroll
    for (int off = 16; off; off >>= 1) {
        ss += __shfl_xor_sync(0xFFFFFFFFu, ss, off);
        sd += __shfl_xor_sync(0xFFFFFFFFu, sd, off);
    }
    if (lane == 0) {
        g_ssrc[row] = ss;
        g_sdst[row] = sd;
    }
}

// ---------------- fused softmax + aggregation (gather, no atomics) --------
// warp per dst node: pass1 warp-max over incoming logits, pass2 accumulate
// exp-weighted feature sum + denominator, epilogue divide/bias/relu.
template <int DO>
__global__ void k_gather(const float* __restrict__ b, int featsel,
                         float* __restrict__ raw, int n) {
    int d = (blockIdx.x * blockDim.x + threadIdx.x) >> 5;
    int lane = threadIdx.x & 31;
    if (d >= n) return;
    int r0 = __ldg(&g_roff[d]);
    int r1 = __ldg(&g_roff[d + 1]);
    float sd = g_sdst[d];

    // pass 1: segment max (lane-strided)
    float m = -CUDART_INF_F;
    for (int j = r0 + lane; j < r1; j += 32) {
        int s = __ldg(&g_adj[j]);
        float e = __ldg(&g_ssrc[s]) + sd;
        e = e > 0.f ? e : 0.2f * e;
        m = fmaxf(m, e);
    }
#pragma unroll
    for (int off = 16; off; off >>= 1)
        m = fmaxf(m, __shfl_xor_sync(0xFFFFFFFFu, m, off));

    // pass 2: denominator + weighted feature accumulation
    float den = 0.f, acc0 = 0.f, acc1 = 0.f;
    for (int j = r0; j < r1; j++) {
        int s = __ldg(&g_adj[j]);  // broadcast
        float e = __ldg(&g_ssrc[s]) + sd;
        e = e > 0.f ? e : 0.2f * e;
        float ex = __expf(e - m);
        den += ex;
        const float* hr = g_h + s * DO;
        acc0 = fmaf(ex, __ldg(hr + lane), acc0);
        if (DO == 64) acc1 = fmaf(ex, __ldg(hr + lane + 32), acc1);
    }
    float inv = 1.f / (den + 1e-16f);
    float v0 = acc0 * inv + __ldg(b + lane);
    float v1 = 0.f;
    if (DO == 64) v1 = acc1 * inv + __ldg(b + lane + 32);

    float* feat = pick_dst(featsel);
    if (raw) {
        raw[d * DO + lane] = v0;
        if (DO == 64) raw[d * DO + lane + 32] = v1;
    }
    if (feat) {
        feat[d * DO + lane] = v0 > 0.f ? v0 : 0.f;
        if (DO == 64) feat[d * DO + lane + 32] = v1 > 0.f ? v1 : 0.f;
    }
}

// ---------------- launch ----------------
extern "C" void kernel_launch(void* const* d_in, const int* in_sizes, int n_in,
                              void* d_out, int out_size) {
    const float* x = (const float*)d_in[0];
    const void* ei = d_in[1];
    const float* w1 = (const float*)d_in[2];
    const float* as1 = (const float*)d_in[3];
    const float* ad1 = (const float*)d_in[4];
    const float* b1 = (const float*)d_in[5];
    const float* w2 = (const float*)d_in[6];
    const float* as2 = (const float*)d_in[7];
    const float* ad2 = (const float*)d_in[8];
    const float* b2 = (const float*)d_in[9];
    const float* w3 = (const float*)d_in[10];
    const float* as3 = (const float*)d_in[11];
    const float* ad3 = (const float*)d_in[12];
    const float* b3 = (const float*)d_in[13];
    const float* w4 = (const float*)d_in[14];
    const float* as4 = (const float*)d_in[15];
    const float* ad4 = (const float*)d_in[16];
    const float* b4 = (const float*)d_in[17];

    int n = in_sizes[0] / 64;
    int eraw = in_sizes[1] / 2;
    int etot = eraw + n;

    float* out_sec = (float*)d_out;         // [n*64]
    float* h_sec = (float*)d_out + n * 64;  // [n*32]

    int nbE = (etot + 255) / 256;
    int nbN = (n + 255) / 256;
    int nbW = (n * 32 + 511) / 512;  // warp-per-row/node kernels, 512 thr

    // graph prep (once per call)
    k_detect<<<1, 32>>>((const unsigned int*)ei, in_sizes[1]);
    k_convert<<<nbE, 256>>>(ei, eraw, n);
    k_zero<<<nbN, 256>>>(n);
    k_hist<<<nbE, 256>>>(etot);
    k_scan<<<1, 1024>>>(n);
    k_scatter<<<nbE, 256>>>(etot);

    // layer 1: x 64->64, relu -> featA
    k_gemm_sc<64, 64><<<nbW, 512>>>(0, x, w1, as1, ad1, n);
    k_gather<64><<<nbW, 512>>>(b1, 1, nullptr, n);

    // layer 2: featA 64->32, raw h -> d_out, relu -> featB
    k_gemm_sc<64, 32><<<nbW, 512>>>(1, nullptr, w2, as2, ad2, n);
    k_gather<32><<<nbW, 512>>>(b2, 2, h_sec, n);

    // layer 3: featB 32->64, relu -> featA
    k_gemm_sc<32, 64><<<nbW, 512>>>(2, nullptr, w3, as3, ad3, n);
    k_gather<64><<<nbW, 512>>>(b3, 1, nullptr, n);

    // layer 4: featA 64->64, raw -> d_out
    k_gemm_sc<64, 64><<<nbW, 512>>>(1, nullptr, w4, as4, ad4, n);
    k_gather<64><<<nbW, 512>>>(b4, 0, out_sec, n);
}

// round 7
// speedup vs baseline: 1.8536x; 1.3410x over previous
#include <cuda_runtime.h>
#include <math_constants.h>

// GAT autoencoder, CSR-gather formulation.
// Layers: 64->64 relu, 64->32 [h out], relu, 32->64 relu, 64->64 [out].
// Outputs concatenated: out [N*64] then h [N*32].

#define MAXN 50000
#define MAXE 800000
#define MAXET (MAXE + MAXN)
#define MAXBLK 64  // scan blocks: ceil(50000/1024) = 49

// ---------------- scratch ----------------
__device__ __align__(16) float g_featA[MAXN * 64];
__device__ __align__(16) float g_featB[MAXN * 64];
__device__ __align__(16) float g_h[MAXN * 64];
__device__ float g_ssrc[MAXN];
__device__ float g_sdst[MAXN];
__device__ float g_e[MAXET];      // per-CSR-slot ssrc[adj[j]]
__device__ int g_src[MAXET];
__device__ int g_dst[MAXET];
__device__ int g_adj[MAXET];      // CSR: src ids grouped by dst
__device__ int g_roff[MAXN + 1];  // CSR row offsets
__device__ int g_cnt[MAXN];
__device__ int g_cur[MAXN];
__device__ int g_bt[MAXBLK];      // scan block totals
__device__ int g_boff[MAXBLK];    // scan block offsets
__device__ int g_is64;

__device__ __forceinline__ const float* pick_src(int sel, const float* ext) {
    if (sel == 1) return g_featA;
    if (sel == 2) return g_featB;
    return ext;
}
__device__ __forceinline__ float* pick_dst(int sel) {
    if (sel == 1) return g_featA;
    if (sel == 2) return g_featB;
    return nullptr;
}

// ---------------- graph prep ----------------

__global__ void k_detect(const unsigned int* __restrict__ w, int nelem) {
    if (threadIdx.x != 0 || blockIdx.x != 0) return;
    int lim = 2 * nelem < 256 ? 2 * nelem : 256;
    int all0 = 1;
    for (int i = 1; i < lim; i += 2)
        if (w[i] != 0) { all0 = 0; break; }
    g_is64 = all0;
}

__global__ void k_convert(const void* __restrict__ ei, int eraw, int n) {
    int i = blockIdx.x * 256 + threadIdx.x;
    int etot = eraw + n;
    if (i >= etot) return;
    if (i < eraw) {
        int s, d;
        if (g_is64) {
            const long long* p = (const long long*)ei;
            s = (int)p[i];
            d = (int)p[eraw + i];
        } else {
            const int* p = (const int*)ei;
            s = p[i];
            d = p[eraw + i];
        }
        s = s < 0 ? 0 : (s >= n ? n - 1 : s);
        d = d < 0 ? 0 : (d >= n ? n - 1 : d);
        g_src[i] = s;
        g_dst[i] = d;
    } else {
        int v = i - eraw;
        g_src[i] = v;
        g_dst[i] = v;
    }
}

__global__ void k_zero(int n) {
    int i = blockIdx.x * 256 + threadIdx.x;
    if (i < n) g_cnt[i] = 0;
}

__global__ void k_hist(int etot) {
    int i = blockIdx.x * 256 + threadIdx.x;
    if (i < etot) atomicAdd(&g_cnt[g_dst[i]], 1);
}

// --- two-level exclusive scan of g_cnt (1024 elems per block) ---
__global__ void k_scan_bt(int n) {
    int base = blockIdx.x * 1024;
    int i0 = base + threadIdx.x * 4;
    int t = 0;
#pragma unroll
    for (int c = 0; c < 4; c++) t += (i0 + c < n) ? g_cnt[i0 + c] : 0;
    int lane = threadIdx.x & 31, wid = threadIdx.x >> 5;
#pragma unroll
    for (int off = 16; off; off >>= 1) t += __shfl_xor_sync(~0u, t, off);
    __shared__ int ws[8];
    if (lane == 0) ws[wid] = t;
    __syncthreads();
    if (threadIdx.x == 0) {
        int s = 0;
#pragma unroll
        for (int w = 0; w < 8; w++) s += ws[w];
        g_bt[blockIdx.x] = s;
    }
}

__global__ void k_scan_mid(int nblk, int n) {
    int lane = threadIdx.x;
    int carry = 0;
    for (int base = 0; base < nblk; base += 32) {
        int i = base + lane;
        int v = (i < nblk) ? g_bt[i] : 0;
        int incl = v;
#pragma unroll
        for (int off = 1; off < 32; off <<= 1) {
            int t = __shfl_up_sync(~0u, incl, off);
            if (lane >= off) incl += t;
        }
        if (i < nblk) g_boff[i] = carry + incl - v;
        carry += __shfl_sync(~0u, incl, 31);
    }
    if (lane == 0) g_roff[n] = carry;
}

__global__ void k_scan_wr(int n) {
    int base = blockIdx.x * 1024;
    int i0 = base + threadIdx.x * 4;
    int v[4], tsum = 0;
#pragma unroll
    for (int c = 0; c < 4; c++) {
        v[c] = (i0 + c < n) ? g_cnt[i0 + c] : 0;
        tsum += v[c];
    }
    int lane = threadIdx.x & 31, wid = threadIdx.x >> 5;
    int incl = tsum;
#pragma unroll
    for (int off = 1; off < 32; off <<= 1) {
        int t = __shfl_up_sync(~0u, incl, off);
        if (lane >= off) incl += t;
    }
    __shared__ int ws[8];
    if (lane == 31) ws[wid] = incl;
    __syncthreads();
    int woff = 0;
    for (int w = 0; w < wid; w++) woff += ws[w];
    int ex = g_boff[blockIdx.x] + woff + incl - tsum;
#pragma unroll
    for (int c = 0; c < 4; c++) {
        if (i0 + c < n) {
            g_roff[i0 + c] = ex;
            g_cur[i0 + c] = ex;
            ex += v[c];
        }
    }
}

__global__ void k_scatter(int etot) {
    int i = blockIdx.x * 256 + threadIdx.x;
    if (i >= etot) return;
    int pos = atomicAdd(&g_cur[g_dst[i]], 1);
    g_adj[pos] = g_src[i];
}

// ---------------- fused gemm + attention scores ----------------
template <int DI, int DO>
__global__ void k_gemm_sc(int xsel, const float* __restrict__ xext,
                          const float* __restrict__ W,
                          const float* __restrict__ as_,
                          const float* __restrict__ ad_, int n) {
    __shared__ float Ws[DI * DO];
    for (int i = threadIdx.x; i < DI * DO; i += blockDim.x) Ws[i] = W[i];
    __syncthreads();
    int row = (blockIdx.x * blockDim.x + threadIdx.x) >> 5;
    int lane = threadIdx.x & 31;
    if (row >= n) return;
    const float* x = pick_src(xsel, xext) + row * DI;
    float acc0 = 0.f, acc1 = 0.f;
#pragma unroll
    for (int k0 = 0; k0 < DI; k0 += 32) {
        float xv = x[k0 + lane];
#pragma unroll
        for (int kk = 0; kk < 32; kk++) {
            float xk = __shfl_sync(0xFFFFFFFFu, xv, kk);
            acc0 = fmaf(xk, Ws[(k0 + kk) * DO + lane], acc0);
            if (DO == 64) acc1 = fmaf(xk, Ws[(k0 + kk) * DO + lane + 32], acc1);
        }
    }
    g_h[row * DO + lane] = acc0;
    if (DO == 64) g_h[row * DO + lane + 32] = acc1;
    float ss = acc0 * __ldg(as_ + lane);
    float sd = acc0 * __ldg(ad_ + lane);
    if (DO == 64) {
        ss = fmaf(acc1, __ldg(as_ + lane + 32), ss);
        sd = fmaf(acc1, __ldg(ad_ + lane + 32), sd);
    }
#pragma unroll
    for (int off = 16; off; off >>= 1) {
        ss += __shfl_xor_sync(0xFFFFFFFFu, ss, off);
        sd += __shfl_xor_sync(0xFFFFFFFFu, sd, off);
    }
    if (lane == 0) {
        g_ssrc[row] = ss;
        g_sdst[row] = sd;
    }
}

// per-CSR-slot source score prefetch (flat, full MLP, coalesced writes)
__global__ void k_edgepre(int etot) {
    int j = blockIdx.x * 256 + threadIdx.x;
    if (j < etot) g_e[j] = __ldg(&g_ssrc[__ldg(&g_adj[j])]);
}

// ---------------- fused softmax + aggregation ----------------
// warp per dst node; two half-warps process even/odd edges; each lane
// covers C = DO/16 columns via one vector load per edge.
template <int DO>
__global__ void k_gather(const float* __restrict__ b, int featsel,
                         float* __restrict__ raw, int n) {
    const int C = DO / 16;  // 4 (DO=64) or 2 (DO=32)
    int d = (blockIdx.x * blockDim.x + threadIdx.x) >> 5;
    int lane = threadIdx.x & 31;
    int half = lane >> 4, l16 = lane & 15;
    if (d >= n) return;
    int r0 = __ldg(&g_roff[d]);
    int r1 = __ldg(&g_roff[d + 1]);
    float sd = g_sdst[d];

    // pass 1: segment max over contiguous e (coalesced)
    float m = -CUDART_INF_F;
    for (int j = r0 + lane; j < r1; j += 32) {
        float e = __ldg(&g_e[j]) + sd;
        e = e > 0.f ? e : 0.2f * e;
        m = fmaxf(m, e);
    }
#pragma unroll
    for (int off = 16; off; off >>= 1)
        m = fmaxf(m, __shfl_xor_sync(0xFFFFFFFFu, m, off));

    // pass 2: each half-warp handles alternating edges
    float den = 0.f;
    float acc[C];
#pragma unroll
    for (int c = 0; c < C; c++) acc[c] = 0.f;
    for (int j = r0 + half; j < r1; j += 2) {
        int s = __ldg(&g_adj[j]);
        float e = __ldg(&g_e[j]) + sd;
        e = e > 0.f ? e : 0.2f * e;
        float ex = __expf(e - m);
        den += ex;
        float hv[C];
        if (C == 4) {
            float4 t = __ldg(reinterpret_cast<const float4*>(g_h + s * DO) + l16);
            hv[0] = t.x; hv[1] = t.y; hv[2] = t.z; hv[3] = t.w;
        } else {
            float2 t = __ldg(reinterpret_cast<const float2*>(g_h + s * DO) + l16);
            hv[0] = t.x; hv[1] = t.y;
        }
#pragma unroll
        for (int c = 0; c < C; c++) acc[c] = fmaf(ex, hv[c], acc[c]);
    }
    // merge the two halves
    den += __shfl_xor_sync(0xFFFFFFFFu, den, 16);
#pragma unroll
    for (int c = 0; c < C; c++) acc[c] += __shfl_xor_sync(0xFFFFFFFFu, acc[c], 16);

    if (half == 0) {
        float inv = 1.f / (den + 1e-16f);
        float v[C];
#pragma unroll
        for (int c = 0; c < C; c++)
            v[c] = acc[c] * inv + __ldg(b + l16 * C + c);
        float* feat = pick_dst(featsel);
        if (raw) {
            if (C == 4)
                reinterpret_cast<float4*>(raw + d * DO)[l16] =
                    make_float4(v[0], v[1], v[2], v[3]);
            else
                reinterpret_cast<float2*>(raw + d * DO)[l16] =
                    make_float2(v[0], v[1]);
        }
        if (feat) {
#pragma unroll
            for (int c = 0; c < C; c++) v[c] = v[c] > 0.f ? v[c] : 0.f;
            if (C == 4)
                reinterpret_cast<float4*>(feat + d * DO)[l16] =
                    make_float4(v[0], v[1], v[2], v[3]);
            else
                reinterpret_cast<float2*>(feat + d * DO)[l16] =
                    make_float2(v[0], v[1]);
        }
    }
}

// ---------------- launch ----------------
extern "C" void kernel_launch(void* const* d_in, const int* in_sizes, int n_in,
                              void* d_out, int out_size) {
    const float* x = (const float*)d_in[0];
    const void* ei = d_in[1];
    const float* w1 = (const float*)d_in[2];
    const float* as1 = (const float*)d_in[3];
    const float* ad1 = (const float*)d_in[4];
    const float* b1 = (const float*)d_in[5];
    const float* w2 = (const float*)d_in[6];
    const float* as2 = (const float*)d_in[7];
    const float* ad2 = (const float*)d_in[8];
    const float* b2 = (const float*)d_in[9];
    const float* w3 = (const float*)d_in[10];
    const float* as3 = (const float*)d_in[11];
    const float* ad3 = (const float*)d_in[12];
    const float* b3 = (const float*)d_in[13];
    const float* w4 = (const float*)d_in[14];
    const float* as4 = (const float*)d_in[15];
    const float* ad4 = (const float*)d_in[16];
    const float* b4 = (const float*)d_in[17];

    int n = in_sizes[0] / 64;
    int eraw = in_sizes[1] / 2;
    int etot = eraw + n;

    float* out_sec = (float*)d_out;         // [n*64]
    float* h_sec = (float*)d_out + n * 64;  // [n*32]

    int nbE = (etot + 255) / 256;
    int nbN = (n + 255) / 256;
    int nbW = (n * 32 + 511) / 512;
    int nblk = (n + 1023) / 1024;

    // graph prep (once per call)
    k_detect<<<1, 32>>>((const unsigned int*)ei, in_sizes[1]);
    k_convert<<<nbE, 256>>>(ei, eraw, n);
    k_zero<<<nbN, 256>>>(n);
    k_hist<<<nbE, 256>>>(etot);
    k_scan_bt<<<nblk, 256>>>(n);
    k_scan_mid<<<1, 32>>>(nblk, n);
    k_scan_wr<<<nblk, 256>>>(n);
    k_scatter<<<nbE, 256>>>(etot);

    // layer 1: x 64->64, relu -> featA
    k_gemm_sc<64, 64><<<nbW, 512>>>(0, x, w1, as1, ad1, n);
    k_edgepre<<<nbE, 256>>>(etot);
    k_gather<64><<<nbW, 512>>>(b1, 1, nullptr, n);

    // layer 2: featA 64->32, raw h -> d_out, relu -> featB
    k_gemm_sc<64, 32><<<nbW, 512>>>(1, nullptr, w2, as2, ad2, n);
    k_edgepre<<<nbE, 256>>>(etot);
    k_gather<32><<<nbW, 512>>>(b2, 2, h_sec, n);

    // layer 3: featB 32->64, relu -> featA
    k_gemm_sc<32, 64><<<nbW, 512>>>(2, nullptr, w3, as3, ad3, n);
    k_edgepre<<<nbE, 256>>>(etot);
    k_gather<64><<<nbW, 512>>>(b3, 1, nullptr, n);

    // layer 4: featA 64->64, raw -> d_out
    k_gemm_sc<64, 64><<<nbW, 512>>>(1, nullptr, w4, as4, ad4, n);
    k_edgepre<<<nbE, 256>>>(etot);
    k_gather<64><<<nbW, 512>>>(b4, 0, out_sec, n);
}